// round 1
// baseline (speedup 1.0000x reference)
#include <cuda_runtime.h>
#include <cuda_bf16.h>

#define BATCH 1024
#define SEQ   512
#define DIM   768
#define FEAT  2304   // 3*DIM
#define H1DIM 256
#define H2DIM 64
#define NCLS  4

// Scratch (no cudaMalloc allowed)
__device__ float g_feat[BATCH * FEAT];   // [e1 | e2 | cls]
__device__ float g_h1[BATCH * H1DIM];

// ---------------------------------------------------------------------------
// Kernel 1: span means + cls gather.  grid = BATCH, block = 192 (DIM/4 float4)
// Each thread owns one float4 column of D. Two separate streaming loops so the
// loads are independent of the accumulator chain (high MLP).
// ---------------------------------------------------------------------------
__global__ void span_feat_kernel(const float* __restrict__ x,
                                 const int* __restrict__ e1_span,
                                 const int* __restrict__ e2_span) {
    const int b = blockIdx.x;
    const int t = threadIdx.x;           // 0..191

    const int lo1 = e1_span[2 * b];
    const int hi1 = max(e1_span[2 * b + 1], lo1 + 1);
    const int lo2 = e2_span[2 * b];
    const int hi2 = max(e2_span[2 * b + 1], lo2 + 1);

    const float4* __restrict__ xb =
        reinterpret_cast<const float4*>(x) + (size_t)b * (SEQ * (DIM / 4));

    float4 a1 = make_float4(0.f, 0.f, 0.f, 0.f);
    float4 a2 = make_float4(0.f, 0.f, 0.f, 0.f);

    // span 1
    #pragma unroll 4
    for (int pos = lo1; pos < hi1; ++pos) {
        float4 v = __ldg(xb + (size_t)pos * (DIM / 4) + t);
        a1.x += v.x; a1.y += v.y; a1.z += v.z; a1.w += v.w;
    }
    // span 2
    #pragma unroll 4
    for (int pos = lo2; pos < hi2; ++pos) {
        float4 v = __ldg(xb + (size_t)pos * (DIM / 4) + t);
        a2.x += v.x; a2.y += v.y; a2.z += v.z; a2.w += v.w;
    }

    const float c1 = 1.0f / (float)(hi1 - lo1);
    const float c2 = 1.0f / (float)(hi2 - lo2);
    float4 cls = __ldg(xb + t);          // row 0

    float4* f = reinterpret_cast<float4*>(g_feat + (size_t)b * FEAT);
    f[t]                  = make_float4(a1.x * c1, a1.y * c1, a1.z * c1, a1.w * c1);
    f[(DIM / 4) + t]      = make_float4(a2.x * c2, a2.y * c2, a2.z * c2, a2.w * c2);
    f[2 * (DIM / 4) + t]  = cls;
}

// ---------------------------------------------------------------------------
// Kernel 2: h1 = relu(feat @ W1 + b1).  C is 1024x256, K = 2304.
// Tile: BM=32, BN=64, BK=16. 256 threads, each computes 2x4 outputs.
// Grid = (N/64, M/32) = (4, 32) = 128 blocks.
// ---------------------------------------------------------------------------
#define BM 32
#define BN 64
#define BK 16

__global__ __launch_bounds__(256) void gemm1_kernel(const float* __restrict__ W1,
                                                    const float* __restrict__ b1) {
    __shared__ float As[BM][BK + 1];
    __shared__ float Bs[BK][BN];

    const int tid = threadIdx.x;
    const int tx = tid & 15;             // 16 col-groups (4 cols each)
    const int ty = tid >> 4;             // 16 row-groups (2 rows each)

    const int m0 = blockIdx.y * BM;
    const int n0 = blockIdx.x * BN;

    float acc[2][4] = {};

    for (int k0 = 0; k0 < FEAT; k0 += BK) {
        // load A tile: 32x16 = 512 floats, 2 per thread
        #pragma unroll
        for (int i = 0; i < 2; ++i) {
            int e = tid + i * 256;
            int r = e >> 4, c = e & 15;
            As[r][c] = g_feat[(size_t)(m0 + r) * FEAT + k0 + c];
        }
        // load B tile: 16x64 = 1024 floats, 4 per thread (coalesced)
        #pragma unroll
        for (int i = 0; i < 4; ++i) {
            int e = tid + i * 256;
            int r = e >> 6, c = e & 63;
            Bs[r][c] = W1[(size_t)(k0 + r) * H1DIM + n0 + c];
        }
        __syncthreads();

        #pragma unroll
        for (int k = 0; k < BK; ++k) {
            float a0 = As[ty * 2 + 0][k];
            float a1 = As[ty * 2 + 1][k];
            float4 bv = *reinterpret_cast<const float4*>(&Bs[k][tx * 4]);
            acc[0][0] += a0 * bv.x; acc[0][1] += a0 * bv.y;
            acc[0][2] += a0 * bv.z; acc[0][3] += a0 * bv.w;
            acc[1][0] += a1 * bv.x; acc[1][1] += a1 * bv.y;
            acc[1][2] += a1 * bv.z; acc[1][3] += a1 * bv.w;
        }
        __syncthreads();
    }

    float4 bias = *reinterpret_cast<const float4*>(&b1[n0 + tx * 4]);
    #pragma unroll
    for (int i = 0; i < 2; ++i) {
        int row = m0 + ty * 2 + i;
        float4 v;
        v.x = fmaxf(acc[i][0] + bias.x, 0.f);
        v.y = fmaxf(acc[i][1] + bias.y, 0.f);
        v.z = fmaxf(acc[i][2] + bias.z, 0.f);
        v.w = fmaxf(acc[i][3] + bias.w, 0.f);
        *reinterpret_cast<float4*>(&g_h1[(size_t)row * H1DIM + n0 + tx * 4]) = v;
    }
}

// ---------------------------------------------------------------------------
// Kernel 3: h2 = relu(h1 @ W2 + b2); logits = h2 @ W3 + b3; softmax.
// grid = BATCH, block = 64 (thread t owns h2[t]).
// ---------------------------------------------------------------------------
__global__ __launch_bounds__(64) void head_kernel(const float* __restrict__ W2,
                                                  const float* __restrict__ b2,
                                                  const float* __restrict__ W3,
                                                  const float* __restrict__ b3,
                                                  float* __restrict__ out) {
    const int b = blockIdx.x;
    const int t = threadIdx.x;           // 0..63

    __shared__ float sh1[H1DIM];
    __shared__ float sred[NCLS][H2DIM];
    __shared__ float slog[NCLS];

    const float* h1 = g_h1 + (size_t)b * H1DIM;
    for (int i = t; i < H1DIM; i += 64) sh1[i] = h1[i];
    __syncthreads();

    float acc = b2[t];
    #pragma unroll 8
    for (int k = 0; k < H1DIM; ++k) {
        acc += sh1[k] * __ldg(&W2[(size_t)k * H2DIM + t]);
    }
    float h2 = fmaxf(acc, 0.f);

    #pragma unroll
    for (int c = 0; c < NCLS; ++c) {
        sred[c][t] = h2 * __ldg(&W3[t * NCLS + c]);
    }
    __syncthreads();

    if (t < NCLS) {
        float s = b3[t];
        #pragma unroll 8
        for (int k = 0; k < H2DIM; ++k) s += sred[t][k];
        slog[t] = s;
    }
    __syncthreads();

    if (t == 0) {
        float l0 = slog[0], l1 = slog[1], l2 = slog[2], l3 = slog[3];
        float m = fmaxf(fmaxf(l0, l1), fmaxf(l2, l3));
        float e0 = __expf(l0 - m), e1 = __expf(l1 - m);
        float e2 = __expf(l2 - m), e3 = __expf(l3 - m);
        float inv = 1.0f / (e0 + e1 + e2 + e3);
        out[b * NCLS + 0] = e0 * inv;
        out[b * NCLS + 1] = e1 * inv;
        out[b * NCLS + 2] = e2 * inv;
        out[b * NCLS + 3] = e3 * inv;
    }
}

// ---------------------------------------------------------------------------
extern "C" void kernel_launch(void* const* d_in, const int* in_sizes, int n_in,
                              void* d_out, int out_size) {
    const float* x       = (const float*)d_in[0];
    const int*   e1_span = (const int*)  d_in[1];
    const int*   e2_span = (const int*)  d_in[2];
    const float* W1      = (const float*)d_in[3];
    const float* b1      = (const float*)d_in[4];
    const float* W2      = (const float*)d_in[5];
    const float* b2      = (const float*)d_in[6];
    const float* W3      = (const float*)d_in[7];
    const float* b3      = (const float*)d_in[8];
    float* out = (float*)d_out;

    span_feat_kernel<<<BATCH, DIM / 4>>>(x, e1_span, e2_span);
    gemm1_kernel<<<dim3(H1DIM / BN, BATCH / BM), 256>>>(W1, b1);
    head_kernel<<<BATCH, H2DIM>>>(W2, b2, W3, b3, out);
}

// round 4
// speedup vs baseline: 1.6149x; 1.6149x over previous
#include <cuda_runtime.h>
#include <cuda_bf16.h>

#define BATCH 1024
#define SEQ   512
#define DIM   768
#define DV    (DIM / 4)      // 192 float4 per row
#define FEAT  2304           // 3*DIM
#define H1DIM 256
#define H2DIM 64
#define NCLS  4

#define CHUNKS 8
#define CROWS  (SEQ / CHUNKS)   // 64

// Scratch (no cudaMalloc allowed)
__device__ float g_part[BATCH * CHUNKS * 2 * DIM];   // 50 MB partial span sums
__device__ float g_feat[BATCH * FEAT];               // [e1 | e2 | cls]
__device__ float g_h1[BATCH * H1DIM];

#define SPLITK 4
#define KSPLIT (FEAT / SPLITK)   // 576
__device__ float g_gp[SPLITK * BATCH * H1DIM];       // 4 MB gemm partials

// ---------------------------------------------------------------------------
// Kernel 1a: partial span sums. grid = BATCH*CHUNKS, block = 192.
// Each block handles one (batch, 64-row chunk); bounded work -> good balance.
// ---------------------------------------------------------------------------
__global__ __launch_bounds__(192) void span_partial_kernel(
        const float* __restrict__ x,
        const int* __restrict__ e1_span,
        const int* __restrict__ e2_span) {
    const int b = blockIdx.x >> 3;
    const int c = blockIdx.x & 7;
    const int t = threadIdx.x;           // float4 column

    const int lo1r = e1_span[2 * b];
    const int hi1  = max(e1_span[2 * b + 1], lo1r + 1);
    const int lo2r = e2_span[2 * b];
    const int hi2  = max(e2_span[2 * b + 1], lo2r + 1);

    const int r0 = c * CROWS, r1 = r0 + CROWS;
    const int s1lo = max(lo1r, r0), s1hi = min(hi1, r1);
    const int s2lo = max(lo2r, r0), s2hi = min(hi2, r1);

    const float4* __restrict__ xb =
        reinterpret_cast<const float4*>(x) + (size_t)b * (SEQ * DV);

    float4 a1 = make_float4(0.f, 0.f, 0.f, 0.f);
    float4 a2 = make_float4(0.f, 0.f, 0.f, 0.f);

    #pragma unroll 8
    for (int pos = s1lo; pos < s1hi; ++pos) {
        float4 v = __ldg(xb + (size_t)pos * DV + t);
        a1.x += v.x; a1.y += v.y; a1.z += v.z; a1.w += v.w;
    }
    #pragma unroll 8
    for (int pos = s2lo; pos < s2hi; ++pos) {
        float4 v = __ldg(xb + (size_t)pos * DV + t);
        a2.x += v.x; a2.y += v.y; a2.z += v.z; a2.w += v.w;
    }

    float4* p = reinterpret_cast<float4*>(
        g_part + ((size_t)(b * CHUNKS + c) * 2) * DIM);
    p[t]      = a1;
    p[DV + t] = a2;
}

// ---------------------------------------------------------------------------
// Kernel 1b: combine partials -> feat (means + cls). grid = BATCH, block = 192
// ---------------------------------------------------------------------------
__global__ __launch_bounds__(192) void span_combine_kernel(
        const float* __restrict__ x,
        const int* __restrict__ e1_span,
        const int* __restrict__ e2_span) {
    const int b = blockIdx.x;
    const int t = threadIdx.x;

    const int lo1 = e1_span[2 * b];
    const int hi1 = max(e1_span[2 * b + 1], lo1 + 1);
    const int lo2 = e2_span[2 * b];
    const int hi2 = max(e2_span[2 * b + 1], lo2 + 1);
    const float c1 = 1.0f / (float)(hi1 - lo1);
    const float c2 = 1.0f / (float)(hi2 - lo2);

    const float4* p = reinterpret_cast<const float4*>(
        g_part + (size_t)b * CHUNKS * 2 * DIM);

    float4 s1 = make_float4(0.f, 0.f, 0.f, 0.f);
    float4 s2 = make_float4(0.f, 0.f, 0.f, 0.f);
    #pragma unroll
    for (int c = 0; c < CHUNKS; ++c) {
        float4 v1 = __ldg(p + (size_t)c * 2 * DV + t);
        float4 v2 = __ldg(p + (size_t)c * 2 * DV + DV + t);
        s1.x += v1.x; s1.y += v1.y; s1.z += v1.z; s1.w += v1.w;
        s2.x += v2.x; s2.y += v2.y; s2.z += v2.z; s2.w += v2.w;
    }

    const float4* xb = reinterpret_cast<const float4*>(x) + (size_t)b * (SEQ * DV);
    float4 cls = __ldg(xb + t);

    float4* f = reinterpret_cast<float4*>(g_feat + (size_t)b * FEAT);
    f[t]          = make_float4(s1.x * c1, s1.y * c1, s1.z * c1, s1.w * c1);
    f[DV + t]     = make_float4(s2.x * c2, s2.y * c2, s2.z * c2, s2.w * c2);
    f[2 * DV + t] = cls;
}

// ---------------------------------------------------------------------------
// Kernel 2a: split-K GEMM. h1_partial[s] = feat[:, sK:(s+1)K] @ W1[sK:(s+1)K,:]
// BM=BN=64, BK=16, 256 threads, 4x4 per thread. grid = (4, 16, SPLITK).
// ---------------------------------------------------------------------------
#define GBM 64
#define GBN 64
#define GBK 16

__global__ __launch_bounds__(256) void gemm1_split_kernel(
        const float* __restrict__ W1) {
    __shared__ float As[GBK][GBM + 1];   // transposed A tile, padded
    __shared__ float Bs[GBK][GBN];

    const int tid = threadIdx.x;
    const int tx = tid & 15;             // 16 col groups
    const int ty = tid >> 4;             // 16 row groups
    const int m0 = blockIdx.y * GBM;
    const int n0 = blockIdx.x * GBN;
    const int k0base = blockIdx.z * KSPLIT;

    const int la_row = tid >> 2;         // 0..63
    const int la_cg  = tid & 3;          // 0..3 (float4 group)

    float acc[4][4] = {};

    for (int kk = 0; kk < KSPLIT; kk += GBK) {
        const int k0 = k0base + kk;

        // A tile 64x16: one float4 per thread, stored transposed
        {
            float4 v = *reinterpret_cast<const float4*>(
                &g_feat[(size_t)(m0 + la_row) * FEAT + k0 + la_cg * 4]);
            As[la_cg * 4 + 0][la_row] = v.x;
            As[la_cg * 4 + 1][la_row] = v.y;
            As[la_cg * 4 + 2][la_row] = v.z;
            As[la_cg * 4 + 3][la_row] = v.w;
        }
        // B tile 16x64: 4 floats per thread, coalesced
        #pragma unroll
        for (int i = 0; i < 4; ++i) {
            int e = tid + i * 256;
            int r = e >> 6, cc = e & 63;
            Bs[r][cc] = W1[(size_t)(k0 + r) * H1DIM + n0 + cc];
        }
        __syncthreads();

        #pragma unroll
        for (int k = 0; k < GBK; ++k) {
            float a0 = As[k][ty * 4 + 0];
            float a1 = As[k][ty * 4 + 1];
            float a2 = As[k][ty * 4 + 2];
            float a3 = As[k][ty * 4 + 3];
            float4 bv = *reinterpret_cast<const float4*>(&Bs[k][tx * 4]);
            acc[0][0] += a0 * bv.x; acc[0][1] += a0 * bv.y; acc[0][2] += a0 * bv.z; acc[0][3] += a0 * bv.w;
            acc[1][0] += a1 * bv.x; acc[1][1] += a1 * bv.y; acc[1][2] += a1 * bv.z; acc[1][3] += a1 * bv.w;
            acc[2][0] += a2 * bv.x; acc[2][1] += a2 * bv.y; acc[2][2] += a2 * bv.z; acc[2][3] += a2 * bv.w;
            acc[3][0] += a3 * bv.x; acc[3][1] += a3 * bv.y; acc[3][2] += a3 * bv.z; acc[3][3] += a3 * bv.w;
        }
        __syncthreads();
    }

    float* gp = g_gp + (size_t)blockIdx.z * BATCH * H1DIM;
    #pragma unroll
    for (int i = 0; i < 4; ++i) {
        int row = m0 + ty * 4 + i;
        *reinterpret_cast<float4*>(&gp[(size_t)row * H1DIM + n0 + tx * 4]) =
            make_float4(acc[i][0], acc[i][1], acc[i][2], acc[i][3]);
    }
}

// ---------------------------------------------------------------------------
// Kernel 2b: reduce split-K partials + bias + relu -> g_h1.
// 1024*256/4 = 65536 float4; 256 blocks x 256 threads.
// ---------------------------------------------------------------------------
__global__ __launch_bounds__(256) void gemm1_reduce_kernel(
        const float* __restrict__ b1) {
    const int idx = blockIdx.x * 256 + threadIdx.x;    // float4 index
    const int col4 = idx & (H1DIM / 4 - 1);            // float4 col within row

    float4 s = make_float4(0.f, 0.f, 0.f, 0.f);
    #pragma unroll
    for (int sp = 0; sp < SPLITK; ++sp) {
        float4 v = reinterpret_cast<const float4*>(
            g_gp + (size_t)sp * BATCH * H1DIM)[idx];
        s.x += v.x; s.y += v.y; s.z += v.z; s.w += v.w;
    }
    float4 bias = reinterpret_cast<const float4*>(b1)[col4];
    s.x = fmaxf(s.x + bias.x, 0.f);
    s.y = fmaxf(s.y + bias.y, 0.f);
    s.z = fmaxf(s.z + bias.z, 0.f);
    s.w = fmaxf(s.w + bias.w, 0.f);
    reinterpret_cast<float4*>(g_h1)[idx] = s;
}

// ---------------------------------------------------------------------------
// Kernel 3: head, 4 batches per block (W2 register reuse x4).
// grid = BATCH/4, block = 64.
// ---------------------------------------------------------------------------
__global__ __launch_bounds__(64) void head_kernel(
        const float* __restrict__ W2, const float* __restrict__ b2,
        const float* __restrict__ W3, const float* __restrict__ b3,
        float* __restrict__ out) {
    const int b0 = blockIdx.x * 4;
    const int t = threadIdx.x;           // 0..63

    __shared__ float sh1[4][H1DIM];
    __shared__ float sred[4][NCLS][H2DIM];
    __shared__ float slog[4][NCLS];

    for (int i = t; i < 4 * H1DIM; i += 64)
        sh1[i >> 8][i & 255] = g_h1[(size_t)b0 * H1DIM + i];
    __syncthreads();

    float acc0 = b2[t], acc1 = acc0, acc2 = acc0, acc3 = acc0;
    #pragma unroll 8
    for (int k = 0; k < H1DIM; ++k) {
        float w = __ldg(&W2[(size_t)k * H2DIM + t]);
        acc0 += sh1[0][k] * w;
        acc1 += sh1[1][k] * w;
        acc2 += sh1[2][k] * w;
        acc3 += sh1[3][k] * w;
    }
    float h2v[4] = { fmaxf(acc0, 0.f), fmaxf(acc1, 0.f),
                     fmaxf(acc2, 0.f), fmaxf(acc3, 0.f) };

    float w3[NCLS];
    #pragma unroll
    for (int c = 0; c < NCLS; ++c) w3[c] = __ldg(&W3[t * NCLS + c]);

    #pragma unroll
    for (int i = 0; i < 4; ++i)
        #pragma unroll
        for (int c = 0; c < NCLS; ++c)
            sred[i][c][t] = h2v[i] * w3[c];
    __syncthreads();

    if (t < 16) {
        int i = t >> 2, c = t & 3;
        float s = b3[c];
        #pragma unroll 8
        for (int k = 0; k < H2DIM; ++k) s += sred[i][c][k];
        slog[i][c] = s;
    }
    __syncthreads();

    if (t < 4) {
        float l0 = slog[t][0], l1 = slog[t][1], l2 = slog[t][2], l3 = slog[t][3];
        float m = fmaxf(fmaxf(l0, l1), fmaxf(l2, l3));
        float e0 = __expf(l0 - m), e1 = __expf(l1 - m);
        float e2 = __expf(l2 - m), e3 = __expf(l3 - m);
        float inv = 1.0f / (e0 + e1 + e2 + e3);
        float* o = out + (size_t)(b0 + t) * NCLS;
        o[0] = e0 * inv; o[1] = e1 * inv; o[2] = e2 * inv; o[3] = e3 * inv;
    }
}

// ---------------------------------------------------------------------------
extern "C" void kernel_launch(void* const* d_in, const int* in_sizes, int n_in,
                              void* d_out, int out_size) {
    const float* x       = (const float*)d_in[0];
    const int*   e1_span = (const int*)  d_in[1];
    const int*   e2_span = (const int*)  d_in[2];
    const float* W1      = (const float*)d_in[3];
    const float* b1      = (const float*)d_in[4];
    const float* W2      = (const float*)d_in[5];
    const float* b2      = (const float*)d_in[6];
    const float* W3      = (const float*)d_in[7];
    const float* b3      = (const float*)d_in[8];
    float* out = (float*)d_out;

    span_partial_kernel<<<BATCH * CHUNKS, 192>>>(x, e1_span, e2_span);
    span_combine_kernel<<<BATCH, 192>>>(x, e1_span, e2_span);
    gemm1_split_kernel<<<dim3(H1DIM / GBN, BATCH / GBM, SPLITK), 256>>>(W1);
    gemm1_reduce_kernel<<<BATCH * H1DIM / 4 / 256, 256>>>(b1);
    head_kernel<<<BATCH / 4, H2DIM>>>(W2, b2, W3, b3, out);
}

// round 6
// speedup vs baseline: 1.9106x; 1.1831x over previous
#include <cuda_runtime.h>
#include <cuda_bf16.h>

#define BATCH 1024
#define SEQ   512
#define DIM   768
#define DV    (DIM / 4)      // 192 float4 per row
#define FEAT  2304           // 3*DIM
#define H1DIM 256
#define H2DIM 64
#define NCLS  4

#define CHUNKS 8
#define CROWS  (SEQ / CHUNKS)   // 64

// Scratch (no cudaMalloc allowed)
__device__ float g_part[BATCH * CHUNKS * 2 * DIM];   // 50 MB partial span sums
__device__ float g_feat[BATCH * FEAT];               // [e1 | e2 | cls]
__device__ float g_h1[BATCH * H1DIM];

#define SPLITK 8
#define KSPLIT (FEAT / SPLITK)   // 288
__device__ float g_gp[SPLITK * BATCH * H1DIM];       // 8 MB gemm partials

// ---------------------------------------------------------------------------
// Kernel 1a: partial span sums, overlap-aware. grid = BATCH*CHUNKS, block=192.
// Segments (exact cover, disjoint):
//   m0=max(lo1,lo2), m1=min(hi1,hi2)
//   A1=[lo1,min(hi1,m0))->a1   A2=[max(lo1,m1),hi1)->a1
//   B1=[lo2,min(hi2,m0))->a2   B2=[max(lo2,m1),hi2)->a2
//   O =[m0,m1)->both           (empty when disjoint)
// Each clamped to this block's chunk [r0,r1). Overlap region read ONCE.
// ---------------------------------------------------------------------------
__global__ __launch_bounds__(192) void span_partial_kernel(
        const float* __restrict__ x,
        const int* __restrict__ e1_span,
        const int* __restrict__ e2_span) {
    const int b = blockIdx.x >> 3;
    const int c = blockIdx.x & 7;
    const int t = threadIdx.x;           // float4 column

    const int lo1 = e1_span[2 * b];
    const int hi1 = max(e1_span[2 * b + 1], lo1 + 1);
    const int lo2 = e2_span[2 * b];
    const int hi2 = max(e2_span[2 * b + 1], lo2 + 1);

    const int m0 = max(lo1, lo2);
    const int m1 = min(hi1, hi2);

    const int r0 = c * CROWS, r1 = r0 + CROWS;

    const float4* __restrict__ xb =
        reinterpret_cast<const float4*>(x) + (size_t)b * (SEQ * DV);

    float4 a1 = make_float4(0.f, 0.f, 0.f, 0.f);
    float4 a2 = make_float4(0.f, 0.f, 0.f, 0.f);

    // A1: span1-only left
    {
        int lo = max(lo1, r0), hi = min(min(hi1, m0), r1);
        #pragma unroll 4
        for (int pos = lo; pos < hi; ++pos) {
            float4 v = __ldg(xb + (size_t)pos * DV + t);
            a1.x += v.x; a1.y += v.y; a1.z += v.z; a1.w += v.w;
        }
    }
    // A2: span1-only right
    {
        int lo = max(max(lo1, m1), r0), hi = min(hi1, r1);
        #pragma unroll 4
        for (int pos = lo; pos < hi; ++pos) {
            float4 v = __ldg(xb + (size_t)pos * DV + t);
            a1.x += v.x; a1.y += v.y; a1.z += v.z; a1.w += v.w;
        }
    }
    // B1: span2-only left
    {
        int lo = max(lo2, r0), hi = min(min(hi2, m0), r1);
        #pragma unroll 4
        for (int pos = lo; pos < hi; ++pos) {
            float4 v = __ldg(xb + (size_t)pos * DV + t);
            a2.x += v.x; a2.y += v.y; a2.z += v.z; a2.w += v.w;
        }
    }
    // B2: span2-only right
    {
        int lo = max(max(lo2, m1), r0), hi = min(hi2, r1);
        #pragma unroll 4
        for (int pos = lo; pos < hi; ++pos) {
            float4 v = __ldg(xb + (size_t)pos * DV + t);
            a2.x += v.x; a2.y += v.y; a2.z += v.z; a2.w += v.w;
        }
    }
    // O: overlap -> both accumulators (single read)
    {
        int lo = max(m0, r0), hi = min(m1, r1);
        #pragma unroll 4
        for (int pos = lo; pos < hi; ++pos) {
            float4 v = __ldg(xb + (size_t)pos * DV + t);
            a1.x += v.x; a1.y += v.y; a1.z += v.z; a1.w += v.w;
            a2.x += v.x; a2.y += v.y; a2.z += v.z; a2.w += v.w;
        }
    }

    float4* p = reinterpret_cast<float4*>(
        g_part + ((size_t)(b * CHUNKS + c) * 2) * DIM);
    p[t]      = a1;
    p[DV + t] = a2;
}

// ---------------------------------------------------------------------------
// Kernel 1b: combine partials -> feat (means + cls). grid = BATCH, block = 192
// ---------------------------------------------------------------------------
__global__ __launch_bounds__(192) void span_combine_kernel(
        const float* __restrict__ x,
        const int* __restrict__ e1_span,
        const int* __restrict__ e2_span) {
    const int b = blockIdx.x;
    const int t = threadIdx.x;

    const int lo1 = e1_span[2 * b];
    const int hi1 = max(e1_span[2 * b + 1], lo1 + 1);
    const int lo2 = e2_span[2 * b];
    const int hi2 = max(e2_span[2 * b + 1], lo2 + 1);
    const float c1 = 1.0f / (float)(hi1 - lo1);
    const float c2 = 1.0f / (float)(hi2 - lo2);

    const float4* p = reinterpret_cast<const float4*>(
        g_part + (size_t)b * CHUNKS * 2 * DIM);

    float4 s1 = make_float4(0.f, 0.f, 0.f, 0.f);
    float4 s2 = make_float4(0.f, 0.f, 0.f, 0.f);
    #pragma unroll
    for (int c = 0; c < CHUNKS; ++c) {
        float4 v1 = __ldg(p + (size_t)c * 2 * DV + t);
        float4 v2 = __ldg(p + (size_t)c * 2 * DV + DV + t);
        s1.x += v1.x; s1.y += v1.y; s1.z += v1.z; s1.w += v1.w;
        s2.x += v2.x; s2.y += v2.y; s2.z += v2.z; s2.w += v2.w;
    }

    const float4* xb = reinterpret_cast<const float4*>(x) + (size_t)b * (SEQ * DV);
    float4 cls = __ldg(xb + t);

    float4* f = reinterpret_cast<float4*>(g_feat + (size_t)b * FEAT);
    f[t]          = make_float4(s1.x * c1, s1.y * c1, s1.z * c1, s1.w * c1);
    f[DV + t]     = make_float4(s2.x * c2, s2.y * c2, s2.z * c2, s2.w * c2);
    f[2 * DV + t] = cls;
}

// ---------------------------------------------------------------------------
// Kernel 2a: split-K GEMM. BM=BN=64, BK=16, 256 threads, 4x4 per thread.
// As padded to 68 floats/row -> aligned LDS.128; inner k-step = 2 LDS.128 +
// 16 FFMA (FFMA-bound). grid = (4, 16, SPLITK=8) = 512 blocks.
// ---------------------------------------------------------------------------
#define GBM 64
#define GBN 64
#define GBK 16

__global__ __launch_bounds__(256) void gemm1_split_kernel(
        const float* __restrict__ W1) {
    __shared__ float As[GBK][GBM + 4];   // 272B row stride, 16B-aligned
    __shared__ float Bs[GBK][GBN];

    const int tid = threadIdx.x;
    const int tx = tid & 15;             // 16 col groups
    const int ty = tid >> 4;             // 16 row groups
    const int m0 = blockIdx.y * GBM;
    const int n0 = blockIdx.x * GBN;
    const int k0base = blockIdx.z * KSPLIT;

    const int la_row = tid >> 2;         // 0..63
    const int la_cg  = tid & 3;          // 0..3 (float4 group)
    const int lb_r   = tid >> 4;         // 0..15
    const int lb_c4  = tid & 15;         // 0..15 (float4 group)

    float acc[4][4] = {};

    for (int kk = 0; kk < KSPLIT; kk += GBK) {
        const int k0 = k0base + kk;

        // A tile 64x16: one float4 per thread, stored transposed
        {
            float4 v = *reinterpret_cast<const float4*>(
                &g_feat[(size_t)(m0 + la_row) * FEAT + k0 + la_cg * 4]);
            As[la_cg * 4 + 0][la_row] = v.x;
            As[la_cg * 4 + 1][la_row] = v.y;
            As[la_cg * 4 + 2][la_row] = v.z;
            As[la_cg * 4 + 3][la_row] = v.w;
        }
        // B tile 16x64: one float4 per thread, coalesced
        {
            float4 v = *reinterpret_cast<const float4*>(
                &W1[(size_t)(k0 + lb_r) * H1DIM + n0 + lb_c4 * 4]);
            *reinterpret_cast<float4*>(&Bs[lb_r][lb_c4 * 4]) = v;
        }
        __syncthreads();

        #pragma unroll
        for (int k = 0; k < GBK; ++k) {
            float4 av = *reinterpret_cast<const float4*>(&As[k][ty * 4]);
            float4 bv = *reinterpret_cast<const float4*>(&Bs[k][tx * 4]);
            acc[0][0] += av.x * bv.x; acc[0][1] += av.x * bv.y; acc[0][2] += av.x * bv.z; acc[0][3] += av.x * bv.w;
            acc[1][0] += av.y * bv.x; acc[1][1] += av.y * bv.y; acc[1][2] += av.y * bv.z; acc[1][3] += av.y * bv.w;
            acc[2][0] += av.z * bv.x; acc[2][1] += av.z * bv.y; acc[2][2] += av.z * bv.z; acc[2][3] += av.z * bv.w;
            acc[3][0] += av.w * bv.x; acc[3][1] += av.w * bv.y; acc[3][2] += av.w * bv.z; acc[3][3] += av.w * bv.w;
        }
        __syncthreads();
    }

    float* gp = g_gp + (size_t)blockIdx.z * BATCH * H1DIM;
    #pragma unroll
    for (int i = 0; i < 4; ++i) {
        int row = m0 + ty * 4 + i;
        *reinterpret_cast<float4*>(&gp[(size_t)row * H1DIM + n0 + tx * 4]) =
            make_float4(acc[i][0], acc[i][1], acc[i][2], acc[i][3]);
    }
}

// ---------------------------------------------------------------------------
// Kernel 2b: reduce split-K partials + bias + relu -> g_h1.
// ---------------------------------------------------------------------------
__global__ __launch_bounds__(256) void gemm1_reduce_kernel(
        const float* __restrict__ b1) {
    const int idx = blockIdx.x * 256 + threadIdx.x;    // float4 index
    const int col4 = idx & (H1DIM / 4 - 1);            // float4 col within row

    float4 s = make_float4(0.f, 0.f, 0.f, 0.f);
    #pragma unroll
    for (int sp = 0; sp < SPLITK; ++sp) {
        float4 v = reinterpret_cast<const float4*>(
            g_gp + (size_t)sp * BATCH * H1DIM)[idx];
        s.x += v.x; s.y += v.y; s.z += v.z; s.w += v.w;
    }
    float4 bias = reinterpret_cast<const float4*>(b1)[col4];
    s.x = fmaxf(s.x + bias.x, 0.f);
    s.y = fmaxf(s.y + bias.y, 0.f);
    s.z = fmaxf(s.z + bias.z, 0.f);
    s.w = fmaxf(s.w + bias.w, 0.f);
    reinterpret_cast<float4*>(g_h1)[idx] = s;
}

// ---------------------------------------------------------------------------
// Kernel 3: head, 4 batches per block (W2 register reuse x4).
// grid = BATCH/4, block = 64.
// ---------------------------------------------------------------------------
__global__ __launch_bounds__(64) void head_kernel(
        const float* __restrict__ W2, const float* __restrict__ b2,
        const float* __restrict__ W3, const float* __restrict__ b3,
        float* __restrict__ out) {
    const int b0 = blockIdx.x * 4;
    const int t = threadIdx.x;           // 0..63

    __shared__ float sh1[4][H1DIM];
    __shared__ float sred[4][NCLS][H2DIM];
    __shared__ float slog[4][NCLS];

    for (int i = t; i < 4 * H1DIM; i += 64)
        sh1[i >> 8][i & 255] = g_h1[(size_t)b0 * H1DIM + i];
    __syncthreads();

    float acc0 = b2[t], acc1 = acc0, acc2 = acc0, acc3 = acc0;
    #pragma unroll 8
    for (int k = 0; k < H1DIM; ++k) {
        float w = __ldg(&W2[(size_t)k * H2DIM + t]);
        acc0 += sh1[0][k] * w;
        acc1 += sh1[1][k] * w;
        acc2 += sh1[2][k] * w;
        acc3 += sh1[3][k] * w;
    }
    float h2v[4] = { fmaxf(acc0, 0.f), fmaxf(acc1, 0.f),
                     fmaxf(acc2, 0.f), fmaxf(acc3, 0.f) };

    float w3[NCLS];
    #pragma unroll
    for (int c = 0; c < NCLS; ++c) w3[c] = __ldg(&W3[t * NCLS + c]);

    #pragma unroll
    for (int i = 0; i < 4; ++i)
        #pragma unroll
        for (int c = 0; c < NCLS; ++c)
            sred[i][c][t] = h2v[i] * w3[c];
    __syncthreads();

    if (t < 16) {
        int i = t >> 2, c = t & 3;
        float s = b3[c];
        #pragma unroll 8
        for (int k = 0; k < H2DIM; ++k) s += sred[i][c][k];
        slog[i][c] = s;
    }
    __syncthreads();

    if (t < 4) {
        float l0 = slog[t][0], l1 = slog[t][1], l2 = slog[t][2], l3 = slog[t][3];
        float m = fmaxf(fmaxf(l0, l1), fmaxf(l2, l3));
        float e0 = __expf(l0 - m), e1 = __expf(l1 - m);
        float e2 = __expf(l2 - m), e3 = __expf(l3 - m);
        float inv = 1.0f / (e0 + e1 + e2 + e3);
        float* o = out + (size_t)(b0 + t) * NCLS;
        o[0] = e0 * inv; o[1] = e1 * inv; o[2] = e2 * inv; o[3] = e3 * inv;
    }
}

// ---------------------------------------------------------------------------
extern "C" void kernel_launch(void* const* d_in, const int* in_sizes, int n_in,
                              void* d_out, int out_size) {
    const float* x       = (const float*)d_in[0];
    const int*   e1_span = (const int*)  d_in[1];
    const int*   e2_span = (const int*)  d_in[2];
    const float* W1      = (const float*)d_in[3];
    const float* b1      = (const float*)d_in[4];
    const float* W2      = (const float*)d_in[5];
    const float* b2      = (const float*)d_in[6];
    const float* W3      = (const float*)d_in[7];
    const float* b3      = (const float*)d_in[8];
    float* out = (float*)d_out;

    span_partial_kernel<<<BATCH * CHUNKS, 192>>>(x, e1_span, e2_span);
    span_combine_kernel<<<BATCH, 192>>>(x, e1_span, e2_span);
    gemm1_split_kernel<<<dim3(H1DIM / GBN, BATCH / GBM, SPLITK), 256>>>(W1);
    gemm1_reduce_kernel<<<BATCH * H1DIM / 4 / 256, 256>>>(b1);
    head_kernel<<<BATCH / 4, H2DIM>>>(W2, b2, W3, b3, out);
}

// round 8
// speedup vs baseline: 1.9597x; 1.0257x over previous
#include <cuda_runtime.h>
#include <cuda_bf16.h>
#include <cstdint>

#define BATCH 1024
#define SEQ   512
#define DIM   768
#define DV    (DIM / 4)      // 192 float4 per row
#define FEAT  2304           // 3*DIM
#define H1DIM 256
#define H2DIM 64
#define NCLS  4

#define CHUNKS 8
#define CROWS  (SEQ / CHUNKS)   // 64

// Scratch (no cudaMalloc allowed)
__device__ float g_part[BATCH * CHUNKS * 2 * DIM];   // 50 MB partial span sums
__device__ float g_feat[BATCH * FEAT];               // [e1 | e2 | cls]

#define SPLITK 8
#define KSPLIT (FEAT / SPLITK)   // 288
__device__ float g_gp[SPLITK * BATCH * H1DIM];       // 8 MB gemm partials

// f32x2 helpers (FFMA2 is PTX-only; ptxas never auto-fuses)
#define PACKF2(out, lo, hi) \
    asm("mov.b64 %0, {%1, %2};" : "=l"(out) : "r"(__float_as_uint(lo)), "r"(__float_as_uint(hi)))
#define FMAF2(acc, a, b) \
    asm("fma.rn.f32x2 %0, %1, %2, %0;" : "+l"(acc) : "l"(a), "l"(b))
#define UNPACKF2(lo, hi, in) \
    do { unsigned _ulo, _uhi; \
         asm("mov.b64 {%0, %1}, %2;" : "=r"(_ulo), "=r"(_uhi) : "l"(in)); \
         lo = __uint_as_float(_ulo); hi = __uint_as_float(_uhi); } while (0)

// ---------------------------------------------------------------------------
// Kernel 1a: partial span sums, overlap-aware. grid = BATCH*CHUNKS, block=192.
// 5-segment exact cover; overlap region read ONCE feeding both accumulators.
// ---------------------------------------------------------------------------
__global__ __launch_bounds__(192) void span_partial_kernel(
        const float* __restrict__ x,
        const int* __restrict__ e1_span,
        const int* __restrict__ e2_span) {
    const int b = blockIdx.x >> 3;
    const int c = blockIdx.x & 7;
    const int t = threadIdx.x;           // float4 column

    const int lo1 = e1_span[2 * b];
    const int hi1 = max(e1_span[2 * b + 1], lo1 + 1);
    const int lo2 = e2_span[2 * b];
    const int hi2 = max(e2_span[2 * b + 1], lo2 + 1);

    const int m0 = max(lo1, lo2);
    const int m1 = min(hi1, hi2);

    const int r0 = c * CROWS, r1 = r0 + CROWS;

    const float4* __restrict__ xb =
        reinterpret_cast<const float4*>(x) + (size_t)b * (SEQ * DV);

    float4 a1 = make_float4(0.f, 0.f, 0.f, 0.f);
    float4 a2 = make_float4(0.f, 0.f, 0.f, 0.f);

    // A1: span1-only left
    {
        int lo = max(lo1, r0), hi = min(min(hi1, m0), r1);
        #pragma unroll 4
        for (int pos = lo; pos < hi; ++pos) {
            float4 v = __ldg(xb + (size_t)pos * DV + t);
            a1.x += v.x; a1.y += v.y; a1.z += v.z; a1.w += v.w;
        }
    }
    // A2: span1-only right
    {
        int lo = max(max(lo1, m1), r0), hi = min(hi1, r1);
        #pragma unroll 4
        for (int pos = lo; pos < hi; ++pos) {
            float4 v = __ldg(xb + (size_t)pos * DV + t);
            a1.x += v.x; a1.y += v.y; a1.z += v.z; a1.w += v.w;
        }
    }
    // B1: span2-only left
    {
        int lo = max(lo2, r0), hi = min(min(hi2, m0), r1);
        #pragma unroll 4
        for (int pos = lo; pos < hi; ++pos) {
            float4 v = __ldg(xb + (size_t)pos * DV + t);
            a2.x += v.x; a2.y += v.y; a2.z += v.z; a2.w += v.w;
        }
    }
    // B2: span2-only right
    {
        int lo = max(max(lo2, m1), r0), hi = min(hi2, r1);
        #pragma unroll 4
        for (int pos = lo; pos < hi; ++pos) {
            float4 v = __ldg(xb + (size_t)pos * DV + t);
            a2.x += v.x; a2.y += v.y; a2.z += v.z; a2.w += v.w;
        }
    }
    // O: overlap -> both accumulators (single read)
    {
        int lo = max(m0, r0), hi = min(m1, r1);
        #pragma unroll 4
        for (int pos = lo; pos < hi; ++pos) {
            float4 v = __ldg(xb + (size_t)pos * DV + t);
            a1.x += v.x; a1.y += v.y; a1.z += v.z; a1.w += v.w;
            a2.x += v.x; a2.y += v.y; a2.z += v.z; a2.w += v.w;
        }
    }

    float4* p = reinterpret_cast<float4*>(
        g_part + ((size_t)(b * CHUNKS + c) * 2) * DIM);
    p[t]      = a1;
    p[DV + t] = a2;
}

// ---------------------------------------------------------------------------
// Kernel 1b: combine partials -> feat (means + cls). grid = BATCH, block = 192
// ---------------------------------------------------------------------------
__global__ __launch_bounds__(192) void span_combine_kernel(
        const float* __restrict__ x,
        const int* __restrict__ e1_span,
        const int* __restrict__ e2_span) {
    const int b = blockIdx.x;
    const int t = threadIdx.x;

    const int lo1 = e1_span[2 * b];
    const int hi1 = max(e1_span[2 * b + 1], lo1 + 1);
    const int lo2 = e2_span[2 * b];
    const int hi2 = max(e2_span[2 * b + 1], lo2 + 1);
    const float c1 = 1.0f / (float)(hi1 - lo1);
    const float c2 = 1.0f / (float)(hi2 - lo2);

    const float4* p = reinterpret_cast<const float4*>(
        g_part + (size_t)b * CHUNKS * 2 * DIM);

    float4 s1 = make_float4(0.f, 0.f, 0.f, 0.f);
    float4 s2 = make_float4(0.f, 0.f, 0.f, 0.f);
    #pragma unroll
    for (int c = 0; c < CHUNKS; ++c) {
        float4 v1 = __ldg(p + (size_t)c * 2 * DV + t);
        float4 v2 = __ldg(p + (size_t)c * 2 * DV + DV + t);
        s1.x += v1.x; s1.y += v1.y; s1.z += v1.z; s1.w += v1.w;
        s2.x += v2.x; s2.y += v2.y; s2.z += v2.z; s2.w += v2.w;
    }

    const float4* xb = reinterpret_cast<const float4*>(x) + (size_t)b * (SEQ * DV);
    float4 cls = __ldg(xb + t);

    float4* f = reinterpret_cast<float4*>(g_feat + (size_t)b * FEAT);
    f[t]          = make_float4(s1.x * c1, s1.y * c1, s1.z * c1, s1.w * c1);
    f[DV + t]     = make_float4(s2.x * c2, s2.y * c2, s2.z * c2, s2.w * c2);
    f[2 * DV + t] = cls;
}

// ---------------------------------------------------------------------------
// Kernel 2: split-K GEMM with FFMA2 (f32x2) inner loop.
// BM=BN=64, BK=16, 256 threads, 4x4 per thread packed as 2x(2)x4 u64 pairs.
// Per k-step: 2 LDS.128 + 6 packs (ALU) + 8 FFMA2. grid = (4,16,8) = 512.
// ---------------------------------------------------------------------------
#define GBM 64
#define GBN 64
#define GBK 16

__global__ __launch_bounds__(256) void gemm1_split_kernel(
        const float* __restrict__ W1) {
    __shared__ float As[GBK][GBM + 4];   // 272B row stride, 16B-aligned
    __shared__ float Bs[GBK][GBN];

    const int tid = threadIdx.x;
    const int tx = tid & 15;             // 16 col groups
    const int ty = tid >> 4;             // 16 row groups
    const int m0 = blockIdx.y * GBM;
    const int n0 = blockIdx.x * GBN;
    const int k0base = blockIdx.z * KSPLIT;

    const int la_row = tid >> 2;         // 0..63
    const int la_cg  = tid & 3;          // 0..3 (float4 group)
    const int lb_r   = tid >> 4;         // 0..15
    const int lb_c4  = tid & 15;         // 0..15 (float4 group)

    // accp[i2][j]: packed pair (acc[2*i2][j], acc[2*i2+1][j])
    uint64_t accp[2][4];
    #pragma unroll
    for (int i = 0; i < 2; ++i)
        #pragma unroll
        for (int j = 0; j < 4; ++j)
            PACKF2(accp[i][j], 0.f, 0.f);

    for (int kk = 0; kk < KSPLIT; kk += GBK) {
        const int k0 = k0base + kk;

        // A tile 64x16: one float4 per thread, stored transposed
        {
            float4 v = *reinterpret_cast<const float4*>(
                &g_feat[(size_t)(m0 + la_row) * FEAT + k0 + la_cg * 4]);
            As[la_cg * 4 + 0][la_row] = v.x;
            As[la_cg * 4 + 1][la_row] = v.y;
            As[la_cg * 4 + 2][la_row] = v.z;
            As[la_cg * 4 + 3][la_row] = v.w;
        }
        // B tile 16x64: one float4 per thread, coalesced
        {
            float4 v = *reinterpret_cast<const float4*>(
                &W1[(size_t)(k0 + lb_r) * H1DIM + n0 + lb_c4 * 4]);
            *reinterpret_cast<float4*>(&Bs[lb_r][lb_c4 * 4]) = v;
        }
        __syncthreads();

        #pragma unroll
        for (int k = 0; k < GBK; ++k) {
            float4 av = *reinterpret_cast<const float4*>(&As[k][ty * 4]);
            float4 bv = *reinterpret_cast<const float4*>(&Bs[k][tx * 4]);
            uint64_t ap0, ap1, bd0, bd1, bd2, bd3;
            PACKF2(ap0, av.x, av.y);
            PACKF2(ap1, av.z, av.w);
            PACKF2(bd0, bv.x, bv.x);
            PACKF2(bd1, bv.y, bv.y);
            PACKF2(bd2, bv.z, bv.z);
            PACKF2(bd3, bv.w, bv.w);
            FMAF2(accp[0][0], ap0, bd0);
            FMAF2(accp[0][1], ap0, bd1);
            FMAF2(accp[0][2], ap0, bd2);
            FMAF2(accp[0][3], ap0, bd3);
            FMAF2(accp[1][0], ap1, bd0);
            FMAF2(accp[1][1], ap1, bd1);
            FMAF2(accp[1][2], ap1, bd2);
            FMAF2(accp[1][3], ap1, bd3);
        }
        __syncthreads();
    }

    // unpack: acc[4][4]
    float acc[4][4];
    #pragma unroll
    for (int i2 = 0; i2 < 2; ++i2)
        #pragma unroll
        for (int j = 0; j < 4; ++j)
            UNPACKF2(acc[2 * i2][j], acc[2 * i2 + 1][j], accp[i2][j]);

    float* gp = g_gp + (size_t)blockIdx.z * BATCH * H1DIM;
    #pragma unroll
    for (int i = 0; i < 4; ++i) {
        int row = m0 + ty * 4 + i;
        *reinterpret_cast<float4*>(&gp[(size_t)row * H1DIM + n0 + tx * 4]) =
            make_float4(acc[i][0], acc[i][1], acc[i][2], acc[i][3]);
    }
}

// ---------------------------------------------------------------------------
// Kernel 3: fused reduce + head. 4 batches per block, grid = BATCH/4, blk 64.
// sh1 load performs the split-K reduction (+bias, relu) inline from g_gp.
// ---------------------------------------------------------------------------
__global__ __launch_bounds__(64) void head_kernel(
        const float* __restrict__ b1,
        const float* __restrict__ W2, const float* __restrict__ b2,
        const float* __restrict__ W3, const float* __restrict__ b3,
        float* __restrict__ out) {
    const int b0 = blockIdx.x * 4;
    const int t = threadIdx.x;           // 0..63

    __shared__ float sh1[4][H1DIM];
    __shared__ float sred[4][NCLS][H2DIM];
    __shared__ float slog[4][NCLS];

    // 4 batches x 256 = 256 float4; each thread reduces 4 float4 over SPLITK
    #pragma unroll
    for (int i4 = 0; i4 < 4; ++i4) {
        const int i = t + i4 * 64;               // 0..255
        const int gidx = b0 * (H1DIM / 4) + i;   // global float4 index
        float4 s = make_float4(0.f, 0.f, 0.f, 0.f);
        #pragma unroll
        for (int sp = 0; sp < SPLITK; ++sp) {
            float4 v = __ldg(reinterpret_cast<const float4*>(
                g_gp + (size_t)sp * BATCH * H1DIM) + gidx);
            s.x += v.x; s.y += v.y; s.z += v.z; s.w += v.w;
        }
        float4 bias = __ldg(reinterpret_cast<const float4*>(b1) +
                            (i & (H1DIM / 4 - 1)));
        const int bl = i >> 6;                   // batch-local 0..3
        const int c4 = (i & 63) * 4;
        sh1[bl][c4 + 0] = fmaxf(s.x + bias.x, 0.f);
        sh1[bl][c4 + 1] = fmaxf(s.y + bias.y, 0.f);
        sh1[bl][c4 + 2] = fmaxf(s.z + bias.z, 0.f);
        sh1[bl][c4 + 3] = fmaxf(s.w + bias.w, 0.f);
    }
    __syncthreads();

    float acc0 = b2[t], acc1 = acc0, acc2 = acc0, acc3 = acc0;
    #pragma unroll 8
    for (int k = 0; k < H1DIM; ++k) {
        float w = __ldg(&W2[(size_t)k * H2DIM + t]);
        acc0 += sh1[0][k] * w;
        acc1 += sh1[1][k] * w;
        acc2 += sh1[2][k] * w;
        acc3 += sh1[3][k] * w;
    }
    float h2v[4] = { fmaxf(acc0, 0.f), fmaxf(acc1, 0.f),
                     fmaxf(acc2, 0.f), fmaxf(acc3, 0.f) };

    float w3[NCLS];
    #pragma unroll
    for (int c = 0; c < NCLS; ++c) w3[c] = __ldg(&W3[t * NCLS + c]);

    #pragma unroll
    for (int i = 0; i < 4; ++i)
        #pragma unroll
        for (int c = 0; c < NCLS; ++c)
            sred[i][c][t] = h2v[i] * w3[c];
    __syncthreads();

    if (t < 16) {
        int i = t >> 2, c = t & 3;
        float s = b3[c];
        #pragma unroll 8
        for (int k = 0; k < H2DIM; ++k) s += sred[i][c][k];
        slog[i][c] = s;
    }
    __syncthreads();

    if (t < 4) {
        float l0 = slog[t][0], l1 = slog[t][1], l2 = slog[t][2], l3 = slog[t][3];
        float m = fmaxf(fmaxf(l0, l1), fmaxf(l2, l3));
        float e0 = __expf(l0 - m), e1 = __expf(l1 - m);
        float e2 = __expf(l2 - m), e3 = __expf(l3 - m);
        float inv = 1.0f / (e0 + e1 + e2 + e3);
        float* o = out + (size_t)(b0 + t) * NCLS;
        o[0] = e0 * inv; o[1] = e1 * inv; o[2] = e2 * inv; o[3] = e3 * inv;
    }
}

// ---------------------------------------------------------------------------
extern "C" void kernel_launch(void* const* d_in, const int* in_sizes, int n_in,
                              void* d_out, int out_size) {
    const float* x       = (const float*)d_in[0];
    const int*   e1_span = (const int*)  d_in[1];
    const int*   e2_span = (const int*)  d_in[2];
    const float* W1      = (const float*)d_in[3];
    const float* b1      = (const float*)d_in[4];
    const float* W2      = (const float*)d_in[5];
    const float* b2      = (const float*)d_in[6];
    const float* W3      = (const float*)d_in[7];
    const float* b3      = (const float*)d_in[8];
    float* out = (float*)d_out;

    span_partial_kernel<<<BATCH * CHUNKS, 192>>>(x, e1_span, e2_span);
    span_combine_kernel<<<BATCH, 192>>>(x, e1_span, e2_span);
    gemm1_split_kernel<<<dim3(H1DIM / GBN, BATCH / GBM, SPLITK), 256>>>(W1);
    head_kernel<<<BATCH / 4, H2DIM>>>(b1, W2, b2, W3, b3, out);
}